// round 1
// baseline (speedup 1.0000x reference)
#include <cuda_runtime.h>
#include <cstdint>

// ---------------- problem constants ----------------
#define BB 2
#define TT 2048
#define DD 1024
#define LL 4
#define VV 32000
#define HH 4096            // 4*D
#define BT (BB*TT)         // 4096

// ---------------- scratch (device globals; no allocation) ----------------
__device__ float g_x  [BT*DD];      // residual stream
__device__ float g_h  [BT*DD];      // ln output (h / y)
__device__ float g_q  [BT*DD];
__device__ float g_k  [BT*DD];
__device__ float g_v  [BT*DD];
__device__ float g_att[(size_t)BB*TT*TT];   // 33.5 MB
__device__ float g_ff [(size_t)BT*HH];      // 67 MB

// ---------------- embed: x = emb[tok] + pos[t] ----------------
__global__ void embed_kernel(const int* __restrict__ tokens,
                             const float* __restrict__ emb,
                             const float* __restrict__ pos)
{
    int row = blockIdx.x;              // 0..BT-1
    int t   = row % TT;
    int tok = tokens[row];
    const float4* e = (const float4*)(emb + (size_t)tok * DD);
    const float4* p = (const float4*)(pos + (size_t)t   * DD);
    float4*       o = (float4*)(g_x + (size_t)row * DD);
    for (int j = threadIdx.x; j < DD/4; j += blockDim.x) {
        float4 a = e[j], b = p[j];
        o[j] = make_float4(a.x+b.x, a.y+b.y, a.z+b.z, a.w+b.w);
    }
}

// ---------------- layernorm (one 256-thread block per row) ----------------
__global__ void ln_kernel(const float* __restrict__ in, float* __restrict__ out,
                          const float* __restrict__ gam, const float* __restrict__ bet)
{
    int row = blockIdx.x;
    const float* x = in + (size_t)row * DD;
    float s = 0.f, s2 = 0.f;
    for (int j = threadIdx.x; j < DD; j += 256) {
        float v = x[j]; s += v; s2 += v*v;
    }
    #pragma unroll
    for (int o = 16; o; o >>= 1) {
        s  += __shfl_xor_sync(0xffffffffu, s,  o);
        s2 += __shfl_xor_sync(0xffffffffu, s2, o);
    }
    __shared__ float sb[16];
    int wid = threadIdx.x >> 5, lid = threadIdx.x & 31;
    if (lid == 0) { sb[wid] = s; sb[8+wid] = s2; }
    __syncthreads();
    s = 0.f; s2 = 0.f;
    #pragma unroll
    for (int w = 0; w < 8; w++) { s += sb[w]; s2 += sb[8+w]; }
    float mu  = s * (1.f/DD);
    float var = s2 * (1.f/DD) - mu*mu;
    float r   = rsqrtf(var + 1e-5f);
    float* y = out + (size_t)row * DD;
    for (int j = threadIdx.x; j < DD; j += 256)
        y[j] = (x[j] - mu) * r * gam[j] + bet[j];
}

// ---------------- causal softmax (one block per (t,b) row) ----------------
__global__ void softmax_kernel(float* __restrict__ att)
{
    int t = blockIdx.x, b = blockIdx.y;
    float* row = att + ((size_t)b*TT + t) * (size_t)TT;
    int len = t + 1;
    int tid = threadIdx.x;
    __shared__ float sr[8];

    float mx = -1e30f;
    for (int j = tid; j < len; j += 256) mx = fmaxf(mx, row[j]);
    #pragma unroll
    for (int o = 16; o; o >>= 1) mx = fmaxf(mx, __shfl_xor_sync(0xffffffffu, mx, o));
    if ((tid & 31) == 0) sr[tid>>5] = mx;
    __syncthreads();
    mx = sr[0];
    #pragma unroll
    for (int w = 1; w < 8; w++) mx = fmaxf(mx, sr[w]);
    __syncthreads();

    float sum = 0.f;
    for (int j = tid; j < len; j += 256) {
        float e = __expf(row[j] - mx);
        row[j] = e; sum += e;
    }
    #pragma unroll
    for (int o = 16; o; o >>= 1) sum += __shfl_xor_sync(0xffffffffu, sum, o);
    if ((tid & 31) == 0) sr[tid>>5] = sum;
    __syncthreads();
    sum = 0.f;
    #pragma unroll
    for (int w = 0; w < 8; w++) sum += sr[w];
    float inv = __fdividef(1.f, sum);
    for (int j = tid; j < TT; j += 256)
        row[j] = (j < len) ? row[j] * inv : 0.f;
}

// ---------------- SGEMM: C = alpha*(A @ B(^T)) [+bias] [+res] [relu] ----------------
// BM=BN=128, BK=8, 256 threads, 8x8 per thread. All dims multiple of 128/8.
#define GBM 128
#define GBN 128
#define GBK 8

template<bool TRANSB, bool RELU>
__global__ void __launch_bounds__(256)
gemm_kernel(const float* __restrict__ A, const float* __restrict__ Bm,
            float* __restrict__ C,
            int M, int N, int K, float alpha,
            const float* __restrict__ bias, const float* __restrict__ res,
            long long sA, long long sB, long long sC)
{
    A  += (long long)blockIdx.z * sA;
    Bm += (long long)blockIdx.z * sB;
    C  += (long long)blockIdx.z * sC;
    const float* resp = res ? res + (long long)blockIdx.z * sC : nullptr;

    __shared__ float As[GBK][GBM];
    __shared__ float Bs[GBK][GBN];

    int tid = threadIdx.x;
    int tx = tid & 15, ty = tid >> 4;
    int m0 = blockIdx.y * GBM, n0 = blockIdx.x * GBN;

    // A tile load indices (128x8, one float4 per thread)
    int ar = tid >> 1;
    int ac = (tid & 1) * 4;
    const float* Aptr = A + (size_t)(m0 + ar) * K + ac;

    float acc[8][8];
    #pragma unroll
    for (int i = 0; i < 8; i++)
        #pragma unroll
        for (int j = 0; j < 8; j++) acc[i][j] = 0.f;

    for (int k0 = 0; k0 < K; k0 += GBK) {
        float4 av = *(const float4*)(Aptr + k0);
        As[ac+0][ar] = av.x; As[ac+1][ar] = av.y;
        As[ac+2][ar] = av.z; As[ac+3][ar] = av.w;

        if (TRANSB) {
            int br = tid >> 1;            // n within tile
            int bc = (tid & 1) * 4;       // k within tile
            float4 bv = *(const float4*)(Bm + (size_t)(n0 + br) * K + k0 + bc);
            Bs[bc+0][br] = bv.x; Bs[bc+1][br] = bv.y;
            Bs[bc+2][br] = bv.z; Bs[bc+3][br] = bv.w;
        } else {
            int br = tid >> 5;            // k within tile
            int bc = (tid & 31) * 4;      // n within tile
            float4 bv = *(const float4*)(Bm + (size_t)(k0 + br) * N + n0 + bc);
            *(float4*)&Bs[br][bc] = bv;
        }
        __syncthreads();

        #pragma unroll
        for (int k = 0; k < GBK; k++) {
            float a[8], b[8];
            #pragma unroll
            for (int i = 0; i < 8; i++) a[i] = As[k][ty*8 + i];
            #pragma unroll
            for (int j = 0; j < 8; j++) b[j] = Bs[k][tx*8 + j];
            #pragma unroll
            for (int i = 0; i < 8; i++)
                #pragma unroll
                for (int j = 0; j < 8; j++)
                    acc[i][j] = fmaf(a[i], b[j], acc[i][j]);
        }
        __syncthreads();
    }

    #pragma unroll
    for (int i = 0; i < 8; i++) {
        int m = m0 + ty*8 + i;
        #pragma unroll
        for (int j = 0; j < 8; j++) {
            int n = n0 + tx*8 + j;
            float c = acc[i][j] * alpha;
            if (bias) c += bias[n];
            if (resp) c += resp[(size_t)m * N + n];
            if (RELU) c = fmaxf(c, 0.f);
            C[(size_t)m * N + n] = c;
        }
    }
}

// ---------------- host orchestration ----------------
static inline float* sym(const void* s)
{
    void* p = nullptr;
    cudaGetSymbolAddress(&p, s);
    return (float*)p;
}

extern "C" void kernel_launch(void* const* d_in, const int* in_sizes, int n_in,
                              void* d_out, int out_size)
{
    const int*   tokens = (const int*)  d_in[0];
    const float* emb    = (const float*)d_in[1];
    const float* pos    = (const float*)d_in[2];
    const float* Wq     = (const float*)d_in[3];
    const float* Wk     = (const float*)d_in[4];
    const float* Wv     = (const float*)d_in[5];
    const float* w1     = (const float*)d_in[6];
    const float* b1     = (const float*)d_in[7];
    const float* w2     = (const float*)d_in[8];
    const float* b2     = (const float*)d_in[9];
    const float* g1     = (const float*)d_in[10];
    const float* bln1   = (const float*)d_in[11];
    const float* g2     = (const float*)d_in[12];
    const float* bln2   = (const float*)d_in[13];
    const float* projw  = (const float*)d_in[14];
    const float* projb  = (const float*)d_in[15];
    float* out = (float*)d_out;

    float* x   = sym(g_x);
    float* h   = sym(g_h);
    float* q   = sym(g_q);
    float* k   = sym(g_k);
    float* v   = sym(g_v);
    float* att = sym(g_att);
    float* ff  = sym(g_ff);

    const float attn_scale = 1.0f / 32.0f;   // 1/sqrt(D), D=1024

    embed_kernel<<<BT, 256>>>(tokens, emb, pos);

    for (int l = 0; l < LL; l++) {
        // h = LN1(x)
        ln_kernel<<<BT, 256>>>(x, h, g1 + l*DD, bln1 + l*DD);

        // q,k,v = h @ W{q,k,v}[l]      [4096,1024]x[1024,1024]
        dim3 gq(DD/GBN, BT/GBM);
        gemm_kernel<false,false><<<gq, 256>>>(h, Wq + (size_t)l*DD*DD, q,
            BT, DD, DD, 1.f, nullptr, nullptr, 0, 0, 0);
        gemm_kernel<false,false><<<gq, 256>>>(h, Wk + (size_t)l*DD*DD, k,
            BT, DD, DD, 1.f, nullptr, nullptr, 0, 0, 0);
        gemm_kernel<false,false><<<gq, 256>>>(h, Wv + (size_t)l*DD*DD, v,
            BT, DD, DD, 1.f, nullptr, nullptr, 0, 0, 0);

        // att = scale * q @ k^T  (batched over B)
        dim3 ga(TT/GBN, TT/GBM, BB);
        gemm_kernel<true,false><<<ga, 256>>>(q, k, att,
            TT, TT, DD, attn_scale, nullptr, nullptr,
            (long long)TT*DD, (long long)TT*DD, (long long)TT*TT);

        // causal softmax (in place, zeros masked region)
        softmax_kernel<<<dim3(TT, BB), 256>>>(att);

        // x = att @ v + x   (batched)
        dim3 gv(DD/GBN, TT/GBM, BB);
        gemm_kernel<false,false><<<gv, 256>>>(att, v, x,
            TT, DD, TT, 1.f, nullptr, x,
            (long long)TT*TT, (long long)TT*DD, (long long)TT*DD);

        // h(y) = LN2(x)
        ln_kernel<<<BT, 256>>>(x, h, g2 + l*DD, bln2 + l*DD);

        // ff = relu(y @ w1 + b1)      [4096,1024]x[1024,4096]
        dim3 g1d(HH/GBN, BT/GBM);
        gemm_kernel<false,true><<<g1d, 256>>>(h, w1 + (size_t)l*DD*HH, ff,
            BT, HH, DD, 1.f, b1 + (size_t)l*HH, nullptr, 0, 0, 0);

        // x = ff @ w2 + b2 + y        [4096,4096]x[4096,1024]
        dim3 g2d(DD/GBN, BT/GBM);
        gemm_kernel<false,false><<<g2d, 256>>>(ff, w2 + (size_t)l*HH*DD, x,
            BT, DD, HH, 1.f, b2 + (size_t)l*DD, h, 0, 0, 0);
    }

    // logits = x @ proj_w + proj_b    [4096,1024]x[1024,32000]
    dim3 gp(VV/GBN, BT/GBM);
    gemm_kernel<false,false><<<gp, 256>>>(x, projw, out,
        BT, VV, DD, 1.f, projb, nullptr, 0, 0, 0);
}

// round 2
// speedup vs baseline: 3.9137x; 3.9137x over previous
#include <cuda_runtime.h>
#include <cstdint>

// ---------------- problem constants ----------------
#define BB 2
#define TT 2048
#define DD 1024
#define LL 4
#define VV 32000
#define HH 4096            // 4*D
#define BT (BB*TT)         // 4096

// ---------------- scratch (device globals; no allocation) ----------------
__device__ float g_x  [BT*DD];
__device__ float g_h  [BT*DD];
__device__ float g_q  [BT*DD];
__device__ float g_k  [BT*DD];
__device__ float g_v  [BT*DD];
__device__ float g_att[(size_t)BB*TT*TT];   // 33.5 MB
__device__ float g_ff [(size_t)BT*HH];      // 67 MB

// ---------------- embed: x = emb[tok] + pos[t] ----------------
__global__ void embed_kernel(const int* __restrict__ tokens,
                             const float* __restrict__ emb,
                             const float* __restrict__ pos)
{
    int row = blockIdx.x;
    int t   = row % TT;
    int tok = tokens[row];
    const float4* e = (const float4*)(emb + (size_t)tok * DD);
    const float4* p = (const float4*)(pos + (size_t)t   * DD);
    float4*       o = (float4*)(g_x + (size_t)row * DD);
    for (int j = threadIdx.x; j < DD/4; j += blockDim.x) {
        float4 a = e[j], b = p[j];
        o[j] = make_float4(a.x+b.x, a.y+b.y, a.z+b.z, a.w+b.w);
    }
}

// ---------------- layernorm (one 256-thread block per row) ----------------
__global__ void ln_kernel(const float* __restrict__ in, float* __restrict__ out,
                          const float* __restrict__ gam, const float* __restrict__ bet)
{
    int row = blockIdx.x;
    const float* x = in + (size_t)row * DD;
    float s = 0.f, s2 = 0.f;
    for (int j = threadIdx.x; j < DD; j += 256) {
        float v = x[j]; s += v; s2 += v*v;
    }
    #pragma unroll
    for (int o = 16; o; o >>= 1) {
        s  += __shfl_xor_sync(0xffffffffu, s,  o);
        s2 += __shfl_xor_sync(0xffffffffu, s2, o);
    }
    __shared__ float sb[16];
    int wid = threadIdx.x >> 5, lid = threadIdx.x & 31;
    if (lid == 0) { sb[wid] = s; sb[8+wid] = s2; }
    __syncthreads();
    s = 0.f; s2 = 0.f;
    #pragma unroll
    for (int w = 0; w < 8; w++) { s += sb[w]; s2 += sb[8+w]; }
    float mu  = s * (1.f/DD);
    float var = s2 * (1.f/DD) - mu*mu;
    float r   = rsqrtf(var + 1e-5f);
    float* y = out + (size_t)row * DD;
    for (int j = threadIdx.x; j < DD; j += 256)
        y[j] = (x[j] - mu) * r * gam[j] + bet[j];
}

// ---------------- causal softmax (one block per (t,b) row) ----------------
__global__ void softmax_kernel(float* __restrict__ att)
{
    int t = blockIdx.x, b = blockIdx.y;
    float* row = att + ((size_t)b*TT + t) * (size_t)TT;
    int len = t + 1;
    int tid = threadIdx.x;
    __shared__ float sr[8];

    float mx = -1e30f;
    for (int j = tid; j < len; j += 256) mx = fmaxf(mx, row[j]);
    #pragma unroll
    for (int o = 16; o; o >>= 1) mx = fmaxf(mx, __shfl_xor_sync(0xffffffffu, mx, o));
    if ((tid & 31) == 0) sr[tid>>5] = mx;
    __syncthreads();
    mx = sr[0];
    #pragma unroll
    for (int w = 1; w < 8; w++) mx = fmaxf(mx, sr[w]);
    __syncthreads();

    float sum = 0.f;
    for (int j = tid; j < len; j += 256) {
        float e = __expf(row[j] - mx);
        row[j] = e; sum += e;
    }
    #pragma unroll
    for (int o = 16; o; o >>= 1) sum += __shfl_xor_sync(0xffffffffu, sum, o);
    if ((tid & 31) == 0) sr[tid>>5] = sum;
    __syncthreads();
    sum = 0.f;
    #pragma unroll
    for (int w = 0; w < 8; w++) sum += sr[w];
    float inv = __fdividef(1.f, sum);
    for (int j = tid; j < TT; j += 256)
        row[j] = (j < len) ? row[j] * inv : 0.f;
}

// ---------------- tf32 tensor-core GEMM ----------------
// C = alpha*(A @ B(^T)) [+bias] [+res] [relu]
// 128x128x32 block tile, 256 threads (8 warps, 2x4), warp tile 64x32,
// mma.sync.m16n8k8 tf32, cp.async double buffering.
// CAUSAL: 0=none, 1=skip blocks with n0>m0+127 (QK^T), 2=clamp K at m0+128 (AV)

__device__ __forceinline__ uint32_t f2tf(float x) {
    uint32_t u = __float_as_uint(x), r;
    asm("cvt.rna.tf32.f32 %0, %1;" : "=r"(r) : "r"(u));
    return r;
}

__device__ __forceinline__ void mma_tf32(float* d, const uint32_t* a, const uint32_t* b) {
    asm volatile("mma.sync.aligned.m16n8k8.row.col.f32.tf32.tf32.f32 "
        "{%0,%1,%2,%3}, {%4,%5,%6,%7}, {%8,%9}, {%0,%1,%2,%3};"
        : "+f"(d[0]), "+f"(d[1]), "+f"(d[2]), "+f"(d[3])
        : "r"(a[0]), "r"(a[1]), "r"(a[2]), "r"(a[3]), "r"(b[0]), "r"(b[1]));
}

__device__ __forceinline__ void cp16(void* dst, const void* src) {
    uint32_t d = (uint32_t)__cvta_generic_to_shared(dst);
    asm volatile("cp.async.cg.shared.global [%0], [%1], 16;" :: "r"(d), "l"(src));
}

#define GEMM_SMEM 73728

template<bool TRANSB, bool RELU, int CAUSAL>
__global__ void __launch_bounds__(256, 2)
gemm_tc(const float* __restrict__ A, const float* __restrict__ Bm,
        float* __restrict__ C, int M, int N, int K, float alpha,
        const float* __restrict__ bias, const float* __restrict__ res,
        long long strA, long long strB, long long strC)
{
    constexpr int ASZ = 128 * 36;                      // words per A stage (pad->conflict-free)
    constexpr int BSZ = TRANSB ? 128 * 36 : 32 * 136;  // words per B stage

    int m0 = blockIdx.y * 128, n0 = blockIdx.x * 128;
    if (CAUSAL == 1 && n0 > m0 + 127) return;          // fully masked QK^T block
    int kEnd = (CAUSAL == 2) ? min(K, m0 + 128) : K;   // AV: att rows zero past diagonal

    A  += (long long)blockIdx.z * strA;
    Bm += (long long)blockIdx.z * strB;
    C  += (long long)blockIdx.z * strC;
    const float* resp = res ? res + (long long)blockIdx.z * strC : (const float*)nullptr;

    extern __shared__ float smf[];
    float* As = smf;
    float* Bs = smf + 2 * ASZ;

    int tid = threadIdx.x;

    auto stage_load = [&](int k0, int s) {
        float* Ad = As + s * ASZ;
        const float* Ag = A + (size_t)m0 * K + k0;
        #pragma unroll
        for (int i = 0; i < 4; i++) {
            int ch = tid + 256 * i;
            int r = ch >> 3, c = (ch & 7) << 2;            // 128 rows x 8 chunks
            cp16(Ad + r * 36 + c, Ag + (size_t)r * K + c);
        }
        float* Bd = Bs + s * BSZ;
        if (TRANSB) {
            const float* Bg = Bm + (size_t)n0 * K + k0;
            #pragma unroll
            for (int i = 0; i < 4; i++) {
                int ch = tid + 256 * i;
                int r = ch >> 3, c = (ch & 7) << 2;        // 128 n-rows x 8 chunks
                cp16(Bd + r * 36 + c, Bg + (size_t)r * K + c);
            }
        } else {
            const float* Bg = Bm + (size_t)k0 * N + n0;
            #pragma unroll
            for (int i = 0; i < 4; i++) {
                int ch = tid + 256 * i;
                int r = ch >> 5, c = (ch & 31) << 2;       // 32 k-rows x 32 chunks
                cp16(Bd + r * 136 + c, Bg + (size_t)r * N + c);
            }
        }
        asm volatile("cp.async.commit_group;");
    };

    int wid = tid >> 5, lane = tid & 31;
    int wm = wid & 1, wn = wid >> 1;       // warps: 2 (M) x 4 (N)
    int g = lane >> 2, tg = lane & 3;

    float acc[4][4][4];
    #pragma unroll
    for (int i = 0; i < 4; i++)
        #pragma unroll
        for (int j = 0; j < 4; j++)
            #pragma unroll
            for (int r = 0; r < 4; r++) acc[i][j][r] = 0.f;

    int nIter = kEnd / 32;
    stage_load(0, 0);

    for (int it = 0; it < nIter; it++) {
        if (it + 1 < nIter) {
            stage_load((it + 1) * 32, (it + 1) & 1);
            asm volatile("cp.async.wait_group 1;");
        } else {
            asm volatile("cp.async.wait_group 0;");
        }
        __syncthreads();

        const float* At = As + (it & 1) * ASZ;
        const float* Bt = Bs + (it & 1) * BSZ;

        #pragma unroll
        for (int kt = 0; kt < 4; kt++) {
            int kk = kt * 8 + tg;
            uint32_t af[4][4], bf[4][2];
            #pragma unroll
            for (int i = 0; i < 4; i++) {
                int r = wm * 64 + i * 16 + g;
                af[i][0] = f2tf(At[r * 36 + kk]);
                af[i][1] = f2tf(At[(r + 8) * 36 + kk]);
                af[i][2] = f2tf(At[r * 36 + kk + 4]);
                af[i][3] = f2tf(At[(r + 8) * 36 + kk + 4]);
            }
            #pragma unroll
            for (int j = 0; j < 4; j++) {
                int n = wn * 32 + j * 8 + g;
                if (TRANSB) {
                    bf[j][0] = f2tf(Bt[n * 36 + kk]);
                    bf[j][1] = f2tf(Bt[n * 36 + kk + 4]);
                } else {
                    bf[j][0] = f2tf(Bt[kk * 136 + n]);
                    bf[j][1] = f2tf(Bt[(kk + 4) * 136 + n]);
                }
            }
            #pragma unroll
            for (int i = 0; i < 4; i++)
                #pragma unroll
                for (int j = 0; j < 4; j++)
                    mma_tf32(acc[i][j], af[i], bf[j]);
        }
        __syncthreads();
    }

    // epilogue
    #pragma unroll
    for (int i = 0; i < 4; i++) {
        #pragma unroll
        for (int j = 0; j < 4; j++) {
            int m = m0 + wm * 64 + i * 16 + g;
            int n = n0 + wn * 32 + j * 8 + 2 * tg;
            float c00 = acc[i][j][0] * alpha, c01 = acc[i][j][1] * alpha;
            float c10 = acc[i][j][2] * alpha, c11 = acc[i][j][3] * alpha;
            if (bias) {
                float b0 = bias[n], b1 = bias[n + 1];
                c00 += b0; c01 += b1; c10 += b0; c11 += b1;
            }
            if (resp) {
                float2 r0 = *(const float2*)(resp + (size_t)m * N + n);
                float2 r1 = *(const float2*)(resp + (size_t)(m + 8) * N + n);
                c00 += r0.x; c01 += r0.y; c10 += r1.x; c11 += r1.y;
            }
            if (RELU) {
                c00 = fmaxf(c00, 0.f); c01 = fmaxf(c01, 0.f);
                c10 = fmaxf(c10, 0.f); c11 = fmaxf(c11, 0.f);
            }
            *(float2*)(C + (size_t)m * N + n)       = make_float2(c00, c01);
            *(float2*)(C + (size_t)(m + 8) * N + n) = make_float2(c10, c11);
        }
    }
}

// ---------------- host orchestration ----------------
static inline float* sym(const void* s)
{
    void* p = nullptr;
    cudaGetSymbolAddress(&p, s);
    return (float*)p;
}

extern "C" void kernel_launch(void* const* d_in, const int* in_sizes, int n_in,
                              void* d_out, int out_size)
{
    const int*   tokens = (const int*)  d_in[0];
    const float* emb    = (const float*)d_in[1];
    const float* pos    = (const float*)d_in[2];
    const float* Wq     = (const float*)d_in[3];
    const float* Wk     = (const float*)d_in[4];
    const float* Wv     = (const float*)d_in[5];
    const float* w1     = (const float*)d_in[6];
    const float* b1     = (const float*)d_in[7];
    const float* w2     = (const float*)d_in[8];
    const float* b2     = (const float*)d_in[9];
    const float* g1     = (const float*)d_in[10];
    const float* bln1   = (const float*)d_in[11];
    const float* g2     = (const float*)d_in[12];
    const float* bln2   = (const float*)d_in[13];
    const float* projw  = (const float*)d_in[14];
    const float* projb  = (const float*)d_in[15];
    float* out = (float*)d_out;

    float* x   = sym(g_x);
    float* h   = sym(g_h);
    float* q   = sym(g_q);
    float* k   = sym(g_k);
    float* v   = sym(g_v);
    float* att = sym(g_att);
    float* ff  = sym(g_ff);

    cudaFuncSetAttribute(gemm_tc<false,false,0>, cudaFuncAttributeMaxDynamicSharedMemorySize, GEMM_SMEM);
    cudaFuncSetAttribute(gemm_tc<true, false,1>, cudaFuncAttributeMaxDynamicSharedMemorySize, GEMM_SMEM);
    cudaFuncSetAttribute(gemm_tc<false,false,2>, cudaFuncAttributeMaxDynamicSharedMemorySize, GEMM_SMEM);
    cudaFuncSetAttribute(gemm_tc<false,true, 0>, cudaFuncAttributeMaxDynamicSharedMemorySize, GEMM_SMEM);

    const float attn_scale = 1.0f / 32.0f;   // 1/sqrt(D), D=1024

    embed_kernel<<<BT, 256>>>(tokens, emb, pos);

    for (int l = 0; l < LL; l++) {
        ln_kernel<<<BT, 256>>>(x, h, g1 + l*DD, bln1 + l*DD);

        dim3 gq(DD/128, BT/128);
        gemm_tc<false,false,0><<<gq, 256, GEMM_SMEM>>>(h, Wq + (size_t)l*DD*DD, q,
            BT, DD, DD, 1.f, nullptr, nullptr, 0, 0, 0);
        gemm_tc<false,false,0><<<gq, 256, GEMM_SMEM>>>(h, Wk + (size_t)l*DD*DD, k,
            BT, DD, DD, 1.f, nullptr, nullptr, 0, 0, 0);
        gemm_tc<false,false,0><<<gq, 256, GEMM_SMEM>>>(h, Wv + (size_t)l*DD*DD, v,
            BT, DD, DD, 1.f, nullptr, nullptr, 0, 0, 0);

        // att = scale * q @ k^T (batched, causal block-skip)
        dim3 ga(TT/128, TT/128, BB);
        gemm_tc<true,false,1><<<ga, 256, GEMM_SMEM>>>(q, k, att,
            TT, TT, DD, attn_scale, nullptr, nullptr,
            (long long)TT*DD, (long long)TT*DD, (long long)TT*TT);

        softmax_kernel<<<dim3(TT, BB), 256>>>(att);

        // x = att @ v + x (batched, K clamped to diagonal)
        dim3 gv(DD/128, TT/128, BB);
        gemm_tc<false,false,2><<<gv, 256, GEMM_SMEM>>>(att, v, x,
            TT, DD, TT, 1.f, nullptr, x,
            (long long)TT*TT, (long long)TT*DD, (long long)TT*DD);

        ln_kernel<<<BT, 256>>>(x, h, g2 + l*DD, bln2 + l*DD);

        // ff = relu(y @ w1 + b1)
        dim3 g1d(HH/128, BT/128);
        gemm_tc<false,true,0><<<g1d, 256, GEMM_SMEM>>>(h, w1 + (size_t)l*DD*HH, ff,
            BT, HH, DD, 1.f, b1 + (size_t)l*HH, nullptr, 0, 0, 0);

        // x = ff @ w2 + b2 + y
        dim3 g2d(DD/128, BT/128);
        gemm_tc<false,false,0><<<g2d, 256, GEMM_SMEM>>>(ff, w2 + (size_t)l*HH*DD, x,
            BT, DD, HH, 1.f, b2 + (size_t)l*DD, h, 0, 0, 0);
    }

    // logits = x @ proj_w + proj_b
    dim3 gp(VV/128, BT/128);
    gemm_tc<false,false,0><<<gp, 256, GEMM_SMEM>>>(x, projw, out,
        BT, VV, DD, 1.f, projb, nullptr, 0, 0, 0);
}

// round 3
// speedup vs baseline: 4.0219x; 1.0277x over previous
#include <cuda_runtime.h>
#include <cstdint>

// ---------------- problem constants ----------------
#define BB 2
#define TT 2048
#define DD 1024
#define LL 4
#define VV 32000
#define HH 4096            // 4*D
#define BT (BB*TT)         // 4096

// ---------------- scratch (device globals; no allocation) ----------------
__device__ float g_x  [BT*DD];              // residual stream (full fp32)
__device__ float g_xr [BT*DD];              // rounded copy of x (for final proj)
__device__ float g_h  [BT*DD];              // LN output (full, for FFN residual)
__device__ float g_hr [BT*DD];              // LN output rounded (GEMM input)
__device__ float g_q  [BT*DD];
__device__ float g_k  [BT*DD];
__device__ float g_v  [BT*DD];
__device__ float g_att[(size_t)BB*TT*TT];   // 33.5 MB
__device__ float g_ff [(size_t)BT*HH];      // 67 MB
// rounded weights
__device__ float g_wq [LL*DD*DD];
__device__ float g_wk [LL*DD*DD];
__device__ float g_wv [LL*DD*DD];
__device__ float g_w1 [(size_t)LL*DD*HH];
__device__ float g_w2 [(size_t)LL*HH*DD];
__device__ float g_pw [(size_t)DD*VV];

__device__ __forceinline__ float tf32r(float x) {
    uint32_t u = __float_as_uint(x), r;
    asm("cvt.rna.tf32.f32 %0, %1;" : "=r"(r) : "r"(u));
    return __uint_as_float(r);
}

// ---------------- weight rounding prepass ----------------
__global__ void round_kernel(const float* __restrict__ src, float* __restrict__ dst, int n4)
{
    int i = blockIdx.x * blockDim.x + threadIdx.x;
    if (i < n4) {
        float4 v = ((const float4*)src)[i];
        v.x = tf32r(v.x); v.y = tf32r(v.y); v.z = tf32r(v.z); v.w = tf32r(v.w);
        ((float4*)dst)[i] = v;
    }
}

// ---------------- embed: x = emb[tok] + pos[t] ----------------
__global__ void embed_kernel(const int* __restrict__ tokens,
                             const float* __restrict__ emb,
                             const float* __restrict__ pos)
{
    int row = blockIdx.x;
    int t   = row % TT;
    int tok = tokens[row];
    const float4* e = (const float4*)(emb + (size_t)tok * DD);
    const float4* p = (const float4*)(pos + (size_t)t   * DD);
    float4*       o = (float4*)(g_x + (size_t)row * DD);
    for (int j = threadIdx.x; j < DD/4; j += blockDim.x) {
        float4 a = e[j], b = p[j];
        o[j] = make_float4(a.x+b.x, a.y+b.y, a.z+b.z, a.w+b.w);
    }
}

// ---------------- layernorm: writes full (out) + tf32-rounded (outr) ----------------
__global__ void ln_kernel(const float* __restrict__ in, float* __restrict__ out,
                          float* __restrict__ outr,
                          const float* __restrict__ gam, const float* __restrict__ bet)
{
    int row = blockIdx.x;
    const float* x = in + (size_t)row * DD;
    float s = 0.f, s2 = 0.f;
    for (int j = threadIdx.x; j < DD; j += 256) {
        float v = x[j]; s += v; s2 += v*v;
    }
    #pragma unroll
    for (int o = 16; o; o >>= 1) {
        s  += __shfl_xor_sync(0xffffffffu, s,  o);
        s2 += __shfl_xor_sync(0xffffffffu, s2, o);
    }
    __shared__ float sb[16];
    int wid = threadIdx.x >> 5, lid = threadIdx.x & 31;
    if (lid == 0) { sb[wid] = s; sb[8+wid] = s2; }
    __syncthreads();
    s = 0.f; s2 = 0.f;
    #pragma unroll
    for (int w = 0; w < 8; w++) { s += sb[w]; s2 += sb[8+w]; }
    float mu  = s * (1.f/DD);
    float var = s2 * (1.f/DD) - mu*mu;
    float r   = rsqrtf(var + 1e-5f);
    float* y  = out  + (size_t)row * DD;
    float* yr = outr + (size_t)row * DD;
    for (int j = threadIdx.x; j < DD; j += 256) {
        float v = (x[j] - mu) * r * gam[j] + bet[j];
        y[j]  = v;
        yr[j] = tf32r(v);
    }
}

// ---------------- causal softmax (writes tf32-rounded probs) ----------------
__global__ void softmax_kernel(float* __restrict__ att)
{
    int t = blockIdx.x, b = blockIdx.y;
    float* row = att + ((size_t)b*TT + t) * (size_t)TT;
    int len = t + 1;
    int tid = threadIdx.x;
    __shared__ float sr[8];

    float mx = -1e30f;
    for (int j = tid; j < len; j += 256) mx = fmaxf(mx, row[j]);
    #pragma unroll
    for (int o = 16; o; o >>= 1) mx = fmaxf(mx, __shfl_xor_sync(0xffffffffu, mx, o));
    if ((tid & 31) == 0) sr[tid>>5] = mx;
    __syncthreads();
    mx = sr[0];
    #pragma unroll
    for (int w = 1; w < 8; w++) mx = fmaxf(mx, sr[w]);
    __syncthreads();

    float sum = 0.f;
    for (int j = tid; j < len; j += 256) {
        float e = __expf(row[j] - mx);
        row[j] = e; sum += e;
    }
    #pragma unroll
    for (int o = 16; o; o >>= 1) sum += __shfl_xor_sync(0xffffffffu, sum, o);
    if ((tid & 31) == 0) sr[tid>>5] = sum;
    __syncthreads();
    sum = 0.f;
    #pragma unroll
    for (int w = 0; w < 8; w++) sum += sr[w];
    float inv = __fdividef(1.f, sum);
    for (int j = tid; j < TT; j += 256)
        row[j] = (j < len) ? tf32r(row[j] * inv) : 0.f;
}

// ---------------- tf32 tensor-core GEMM (inputs pre-rounded to tf32) ----------------
// C = alpha*(A @ B(^T)) [+bias] [+res] [relu] [round] [aux rounded copy Cr]
// 128x128x32 block tile, 256 threads (8 warps 2x4), warp tile 64x32, mma m16n8k8.
// CAUSAL: 0=none, 1=skip n0>m0+127 (QK^T), 2=clamp K at m0+128 (AV)

__device__ __forceinline__ void mma_tf32(float* d, const uint32_t* a, const uint32_t* b) {
    asm volatile("mma.sync.aligned.m16n8k8.row.col.f32.tf32.tf32.f32 "
        "{%0,%1,%2,%3}, {%4,%5,%6,%7}, {%8,%9}, {%0,%1,%2,%3};"
        : "+f"(d[0]), "+f"(d[1]), "+f"(d[2]), "+f"(d[3])
        : "r"(a[0]), "r"(a[1]), "r"(a[2]), "r"(a[3]), "r"(b[0]), "r"(b[1]));
}

__device__ __forceinline__ void cp16(void* dst, const void* src) {
    uint32_t d = (uint32_t)__cvta_generic_to_shared(dst);
    asm volatile("cp.async.cg.shared.global [%0], [%1], 16;" :: "r"(d), "l"(src));
}

#define GEMM_SMEM 73728

template<bool TRANSB, bool RELU, int CAUSAL, bool ROUND>
__global__ void __launch_bounds__(256, 2)
gemm_tc(const float* __restrict__ A, const float* __restrict__ Bm,
        float* __restrict__ C, float* __restrict__ Cr,
        int M, int N, int K, float alpha,
        const float* __restrict__ bias, const float* __restrict__ res,
        long long strA, long long strB, long long strC)
{
    constexpr int ASZ = 128 * 36;
    constexpr int BSZ = TRANSB ? 128 * 36 : 32 * 136;

    int m0 = blockIdx.y * 128, n0 = blockIdx.x * 128;
    if (CAUSAL == 1 && n0 > m0 + 127) return;
    int kEnd = (CAUSAL == 2) ? min(K, m0 + 128) : K;

    A  += (long long)blockIdx.z * strA;
    Bm += (long long)blockIdx.z * strB;
    C  += (long long)blockIdx.z * strC;
    const float* resp = res ? res + (long long)blockIdx.z * strC : (const float*)nullptr;

    extern __shared__ float smf[];
    float* As = smf;
    float* Bs = smf + 2 * ASZ;

    int tid = threadIdx.x;

    auto stage_load = [&](int k0, int s) {
        float* Ad = As + s * ASZ;
        const float* Ag = A + (size_t)m0 * K + k0;
        #pragma unroll
        for (int i = 0; i < 4; i++) {
            int ch = tid + 256 * i;
            int r = ch >> 3, c = (ch & 7) << 2;
            cp16(Ad + r * 36 + c, Ag + (size_t)r * K + c);
        }
        float* Bd = Bs + s * BSZ;
        if (TRANSB) {
            const float* Bg = Bm + (size_t)n0 * K + k0;
            #pragma unroll
            for (int i = 0; i < 4; i++) {
                int ch = tid + 256 * i;
                int r = ch >> 3, c = (ch & 7) << 2;
                cp16(Bd + r * 36 + c, Bg + (size_t)r * K + c);
            }
        } else {
            const float* Bg = Bm + (size_t)k0 * N + n0;
            #pragma unroll
            for (int i = 0; i < 4; i++) {
                int ch = tid + 256 * i;
                int r = ch >> 5, c = (ch & 31) << 2;
                cp16(Bd + r * 136 + c, Bg + (size_t)r * N + c);
            }
        }
        asm volatile("cp.async.commit_group;");
    };

    int wid = tid >> 5, lane = tid & 31;
    int wm = wid & 1, wn = wid >> 1;
    int g = lane >> 2, tg = lane & 3;

    float acc[4][4][4];
    #pragma unroll
    for (int i = 0; i < 4; i++)
        #pragma unroll
        for (int j = 0; j < 4; j++)
            #pragma unroll
            for (int r = 0; r < 4; r++) acc[i][j][r] = 0.f;

    int nIter = kEnd / 32;
    stage_load(0, 0);

    for (int it = 0; it < nIter; it++) {
        if (it + 1 < nIter) {
            stage_load((it + 1) * 32, (it + 1) & 1);
            asm volatile("cp.async.wait_group 1;");
        } else {
            asm volatile("cp.async.wait_group 0;");
        }
        __syncthreads();

        const uint32_t* At = (const uint32_t*)(As + (it & 1) * ASZ);
        const uint32_t* Bt = (const uint32_t*)(Bs + (it & 1) * BSZ);

        #pragma unroll
        for (int kt = 0; kt < 4; kt++) {
            int kk = kt * 8 + tg;
            uint32_t af[4][4], bf[4][2];
            #pragma unroll
            for (int i = 0; i < 4; i++) {
                int r = wm * 64 + i * 16 + g;
                af[i][0] = At[r * 36 + kk];
                af[i][1] = At[(r + 8) * 36 + kk];
                af[i][2] = At[r * 36 + kk + 4];
                af[i][3] = At[(r + 8) * 36 + kk + 4];
            }
            #pragma unroll
            for (int j = 0; j < 4; j++) {
                int n = wn * 32 + j * 8 + g;
                if (TRANSB) {
                    bf[j][0] = Bt[n * 36 + kk];
                    bf[j][1] = Bt[n * 36 + kk + 4];
                } else {
                    bf[j][0] = Bt[kk * 136 + n];
                    bf[j][1] = Bt[(kk + 4) * 136 + n];
                }
            }
            #pragma unroll
            for (int i = 0; i < 4; i++)
                #pragma unroll
                for (int j = 0; j < 4; j++)
                    mma_tf32(acc[i][j], af[i], bf[j]);
        }
        __syncthreads();
    }

    // epilogue
    #pragma unroll
    for (int i = 0; i < 4; i++) {
        #pragma unroll
        for (int j = 0; j < 4; j++) {
            int m = m0 + wm * 64 + i * 16 + g;
            int n = n0 + wn * 32 + j * 8 + 2 * tg;
            float c00 = acc[i][j][0] * alpha, c01 = acc[i][j][1] * alpha;
            float c10 = acc[i][j][2] * alpha, c11 = acc[i][j][3] * alpha;
            if (bias) {
                float b0 = bias[n], b1 = bias[n + 1];
                c00 += b0; c01 += b1; c10 += b0; c11 += b1;
            }
            if (resp) {
                float2 r0 = *(const float2*)(resp + (size_t)m * N + n);
                float2 r1 = *(const float2*)(resp + (size_t)(m + 8) * N + n);
                c00 += r0.x; c01 += r0.y; c10 += r1.x; c11 += r1.y;
            }
            if (RELU) {
                c00 = fmaxf(c00, 0.f); c01 = fmaxf(c01, 0.f);
                c10 = fmaxf(c10, 0.f); c11 = fmaxf(c11, 0.f);
            }
            if (ROUND) {
                c00 = tf32r(c00); c01 = tf32r(c01);
                c10 = tf32r(c10); c11 = tf32r(c11);
            }
            *(float2*)(C + (size_t)m * N + n)       = make_float2(c00, c01);
            *(float2*)(C + (size_t)(m + 8) * N + n) = make_float2(c10, c11);
            if (Cr) {
                *(float2*)(Cr + (size_t)m * N + n) =
                    make_float2(tf32r(c00), tf32r(c01));
                *(float2*)(Cr + (size_t)(m + 8) * N + n) =
                    make_float2(tf32r(c10), tf32r(c11));
            }
        }
    }
}

// ---------------- host orchestration ----------------
static inline float* sym(const void* s)
{
    void* p = nullptr;
    cudaGetSymbolAddress(&p, s);
    return (float*)p;
}

extern "C" void kernel_launch(void* const* d_in, const int* in_sizes, int n_in,
                              void* d_out, int out_size)
{
    const int*   tokens = (const int*)  d_in[0];
    const float* emb    = (const float*)d_in[1];
    const float* pos    = (const float*)d_in[2];
    const float* Wq     = (const float*)d_in[3];
    const float* Wk     = (const float*)d_in[4];
    const float* Wv     = (const float*)d_in[5];
    const float* w1     = (const float*)d_in[6];
    const float* b1     = (const float*)d_in[7];
    const float* w2     = (const float*)d_in[8];
    const float* b2     = (const float*)d_in[9];
    const float* g1     = (const float*)d_in[10];
    const float* bln1   = (const float*)d_in[11];
    const float* g2     = (const float*)d_in[12];
    const float* bln2   = (const float*)d_in[13];
    const float* projw  = (const float*)d_in[14];
    const float* projb  = (const float*)d_in[15];
    float* out = (float*)d_out;

    float* x   = sym(g_x);
    float* xr  = sym(g_xr);
    float* h   = sym(g_h);
    float* hr  = sym(g_hr);
    float* q   = sym(g_q);
    float* k   = sym(g_k);
    float* v   = sym(g_v);
    float* att = sym(g_att);
    float* ff  = sym(g_ff);
    float* wqr = sym(g_wq);
    float* wkr = sym(g_wk);
    float* wvr = sym(g_wv);
    float* w1r = sym(g_w1);
    float* w2r = sym(g_w2);
    float* pwr = sym(g_pw);

    cudaFuncSetAttribute(gemm_tc<false,false,0,true >, cudaFuncAttributeMaxDynamicSharedMemorySize, GEMM_SMEM);
    cudaFuncSetAttribute(gemm_tc<true, false,1,false>, cudaFuncAttributeMaxDynamicSharedMemorySize, GEMM_SMEM);
    cudaFuncSetAttribute(gemm_tc<false,false,2,false>, cudaFuncAttributeMaxDynamicSharedMemorySize, GEMM_SMEM);
    cudaFuncSetAttribute(gemm_tc<false,true, 0,true >, cudaFuncAttributeMaxDynamicSharedMemorySize, GEMM_SMEM);
    cudaFuncSetAttribute(gemm_tc<false,false,0,false>, cudaFuncAttributeMaxDynamicSharedMemorySize, GEMM_SMEM);

    // ---- weight rounding prepass ----
    {
        int n;
        n = LL*DD*DD/4;
        round_kernel<<<(n+255)/256, 256>>>(Wq, wqr, n);
        round_kernel<<<(n+255)/256, 256>>>(Wk, wkr, n);
        round_kernel<<<(n+255)/256, 256>>>(Wv, wvr, n);
        n = LL*DD*HH/4;
        round_kernel<<<(n+255)/256, 256>>>(w1, w1r, n);
        round_kernel<<<(n+255)/256, 256>>>(w2, w2r, n);
        n = DD*VV/4;
        round_kernel<<<(n+255)/256, 256>>>(projw, pwr, n);
    }

    const float attn_scale = 1.0f / 32.0f;

    embed_kernel<<<BT, 256>>>(tokens, emb, pos);

    for (int l = 0; l < LL; l++) {
        ln_kernel<<<BT, 256>>>(x, h, hr, g1 + l*DD, bln1 + l*DD);

        dim3 gq(DD/128, BT/128);
        gemm_tc<false,false,0,true><<<gq, 256, GEMM_SMEM>>>(hr, wqr + (size_t)l*DD*DD, q, nullptr,
            BT, DD, DD, 1.f, nullptr, nullptr, 0, 0, 0);
        gemm_tc<false,false,0,true><<<gq, 256, GEMM_SMEM>>>(hr, wkr + (size_t)l*DD*DD, k, nullptr,
            BT, DD, DD, 1.f, nullptr, nullptr, 0, 0, 0);
        gemm_tc<false,false,0,true><<<gq, 256, GEMM_SMEM>>>(hr, wvr + (size_t)l*DD*DD, v, nullptr,
            BT, DD, DD, 1.f, nullptr, nullptr, 0, 0, 0);

        // att = scale * q @ k^T (batched, causal block-skip)
        dim3 ga(TT/128, TT/128, BB);
        gemm_tc<true,false,1,false><<<ga, 256, GEMM_SMEM>>>(q, k, att, nullptr,
            TT, TT, DD, attn_scale, nullptr, nullptr,
            (long long)TT*DD, (long long)TT*DD, (long long)TT*TT);

        softmax_kernel<<<dim3(TT, BB), 256>>>(att);

        // x = att @ v + x (batched, K clamped to diagonal)
        dim3 gv(DD/128, TT/128, BB);
        gemm_tc<false,false,2,false><<<gv, 256, GEMM_SMEM>>>(att, v, x, nullptr,
            TT, DD, TT, 1.f, nullptr, x,
            (long long)TT*TT, (long long)TT*DD, (long long)TT*DD);

        ln_kernel<<<BT, 256>>>(x, h, hr, g2 + l*DD, bln2 + l*DD);

        // ff = relu(y @ w1 + b1), rounded
        dim3 g1d(HH/128, BT/128);
        gemm_tc<false,true,0,true><<<g1d, 256, GEMM_SMEM>>>(hr, w1r + (size_t)l*DD*HH, ff, nullptr,
            BT, HH, DD, 1.f, b1 + (size_t)l*HH, nullptr, 0, 0, 0);

        // x = ff @ w2 + b2 + y (full) ; xr = rounded copy for final proj
        dim3 g2d(DD/128, BT/128);
        gemm_tc<false,false,0,false><<<g2d, 256, GEMM_SMEM>>>(ff, w2r + (size_t)l*HH*DD, x, xr,
            BT, DD, HH, 1.f, b2 + (size_t)l*DD, h, 0, 0, 0);
    }

    // logits = xr @ proj_w + proj_b
    dim3 gp(VV/128, BT/128);
    gemm_tc<false,false,0,false><<<gp, 256, GEMM_SMEM>>>(xr, pwr, out, nullptr,
        BT, VV, DD, 1.f, projb, nullptr, 0, 0, 0);
}